// round 7
// baseline (speedup 1.0000x reference)
#include <cuda_runtime.h>
#include <cstdint>

#define S_LEN 512
#define BATCH 32
#define HID 256
#define NTAG 11
#define START_TAG 9
#define STOP_TAG 10
#define NEGV -1000.0f
#define NCTA_LSTM 128

// ---------------- static device scratch ----------------
__device__ float g_xe[S_LEN * BATCH * HID];                 // [s*32+b][256]
__device__ float g_gates[2 * S_LEN * BATCH * 4 * HID];      // [dir][s][b][1024] (reused L0/L1)
__device__ float g_h0[S_LEN * BATCH * 2 * HID];             // [s*32+b][512]
__device__ float g_h1[S_LEN * BATCH * 2 * HID];
__device__ float g_feats[S_LEN * BATCH * NTAG];             // [s*32+b][11]

// ---------------- packed f32x2 helpers ----------------
__device__ __forceinline__ void vfma(unsigned long long& acc,
                                     unsigned long long a, unsigned long long b) {
    asm("fma.rn.f32x2 %0, %1, %2, %0;" : "+l"(acc) : "l"(a), "l"(b));
}
__device__ __forceinline__ unsigned long long dup2(float x) {
    unsigned long long r;
    asm("mov.b64 %0, {%1,%1};" : "=l"(r) : "f"(x));
    return r;
}
__device__ __forceinline__ float2 unpk(unsigned long long v) {
    float2 r;
    asm("mov.b64 {%0,%1}, %2;" : "=f"(r.x), "=f"(r.y) : "l"(v));
    return r;
}
__device__ __forceinline__ float red2(unsigned long long v) {
    float2 r = unpk(v);
    return r.x + r.y;
}

// ---------------- embedding gather ----------------
__global__ __launch_bounds__(256)
void embed_kernel(const int* __restrict__ x,
                  const float* __restrict__ emb,
                  float* __restrict__ xe) {
    int idx = blockIdx.x * 256 + threadIdx.x;   // 16384 rows * 64 float4
    int pos = idx >> 6, h4 = idx & 63;
    int s = pos >> 5, b = pos & 31;
    int tok = x[b * S_LEN + s];
    ((float4*)xe)[((size_t)pos << 6) + h4] = ((const float4*)emb)[(size_t)tok * 64 + h4];
}

// ---------------- SGEMM: C[m][n] = sum_k A[m][k]*W[n][k] + bias[n] ----------------
// 128x128 tile, 256 threads, 8x8 per thread, f32x2 packed over row pairs.
// M = 16384 (grid.y*128), N = 1024 (grid.x*128), C row stride 1024.
__global__ __launch_bounds__(256)
void sgemm_bias(const float* __restrict__ A,
                const float* __restrict__ W,
                const float* __restrict__ bias,
                float* __restrict__ C,
                int K) {
    __shared__ __align__(16) float As[16][128];
    __shared__ __align__(16) float Bs[16][128];
    int tid = threadIdx.x;
    int m0 = blockIdx.y << 7;
    int n0 = blockIdx.x << 7;
    int tx = tid & 15, ty = tid >> 4;           // tx: n, ty: m
    int am = tid >> 1, ah = (tid & 1) << 3;     // A stage: row am, k-offset ah..ah+7

    unsigned long long acc2[4][8];              // [m-pair][n]
#pragma unroll
    for (int p = 0; p < 4; ++p)
#pragma unroll
        for (int j = 0; j < 8; ++j) acc2[p][j] = 0ull;

    const float* Ap = A + (size_t)(m0 + am) * K + ah;
    const float* Wp = W + (size_t)(n0 + am) * K + ah;

    for (int kt = 0; kt < K; kt += 16) {
        float4 av0 = *(const float4*)(Ap + kt);
        float4 av1 = *(const float4*)(Ap + kt + 4);
        float4 bv0 = *(const float4*)(Wp + kt);
        float4 bv1 = *(const float4*)(Wp + kt + 4);
        __syncthreads();
        As[ah + 0][am] = av0.x; As[ah + 1][am] = av0.y;
        As[ah + 2][am] = av0.z; As[ah + 3][am] = av0.w;
        As[ah + 4][am] = av1.x; As[ah + 5][am] = av1.y;
        As[ah + 6][am] = av1.z; As[ah + 7][am] = av1.w;
        Bs[ah + 0][am] = bv0.x; Bs[ah + 1][am] = bv0.y;
        Bs[ah + 2][am] = bv0.z; Bs[ah + 3][am] = bv0.w;
        Bs[ah + 4][am] = bv1.x; Bs[ah + 5][am] = bv1.y;
        Bs[ah + 6][am] = bv1.z; Bs[ah + 7][am] = bv1.w;
        __syncthreads();
#pragma unroll
        for (int k = 0; k < 16; ++k) {
            ulonglong2 aL = *(const ulonglong2*)&As[k][ty << 3];
            ulonglong2 aH = *(const ulonglong2*)&As[k][(ty << 3) + 4];
            float4 b0 = *(const float4*)&Bs[k][tx << 2];
            float4 b1 = *(const float4*)&Bs[k][64 + (tx << 2)];
            unsigned long long bd[8];
            bd[0] = dup2(b0.x); bd[1] = dup2(b0.y); bd[2] = dup2(b0.z); bd[3] = dup2(b0.w);
            bd[4] = dup2(b1.x); bd[5] = dup2(b1.y); bd[6] = dup2(b1.z); bd[7] = dup2(b1.w);
#pragma unroll
            for (int j = 0; j < 8; ++j) {
                vfma(acc2[0][j], aL.x, bd[j]);
                vfma(acc2[1][j], aL.y, bd[j]);
                vfma(acc2[2][j], aH.x, bd[j]);
                vfma(acc2[3][j], aH.y, bd[j]);
            }
        }
    }
    float4 bsv0 = *(const float4*)&bias[n0 + (tx << 2)];
    float4 bsv1 = *(const float4*)&bias[n0 + 64 + (tx << 2)];
#pragma unroll
    for (int p = 0; p < 4; ++p) {
        float2 c0 = unpk(acc2[p][0]), c1 = unpk(acc2[p][1]);
        float2 c2 = unpk(acc2[p][2]), c3 = unpk(acc2[p][3]);
        float2 c4 = unpk(acc2[p][4]), c5 = unpk(acc2[p][5]);
        float2 c6 = unpk(acc2[p][6]), c7 = unpk(acc2[p][7]);
        size_t re = (size_t)(m0 + (ty << 3) + 2 * p) * 1024;
        size_t ro = re + 1024;
        float4 v;
        v.x = c0.x + bsv0.x; v.y = c1.x + bsv0.y; v.z = c2.x + bsv0.z; v.w = c3.x + bsv0.w;
        *(float4*)&C[re + n0 + (tx << 2)] = v;
        v.x = c4.x + bsv1.x; v.y = c5.x + bsv1.y; v.z = c6.x + bsv1.z; v.w = c7.x + bsv1.w;
        *(float4*)&C[re + n0 + 64 + (tx << 2)] = v;
        v.x = c0.y + bsv0.x; v.y = c1.y + bsv0.y; v.z = c2.y + bsv0.z; v.w = c3.y + bsv0.w;
        *(float4*)&C[ro + n0 + (tx << 2)] = v;
        v.x = c4.y + bsv1.x; v.y = c5.y + bsv1.y; v.z = c6.y + bsv1.z; v.w = c7.y + bsv1.w;
        *(float4*)&C[ro + n0 + 64 + (tx << 2)] = v;
    }
}

// ---------------- persistent BiLSTM layer (cluster-8, DSMEM h exchange) ----------------
__device__ __forceinline__ float sigm(float x) { return 1.f / (1.f + __expf(-x)); }

#define CLUSTER_SYNC_() do { \
    asm volatile("barrier.cluster.arrive.aligned;" ::: "memory"); \
    asm volatile("barrier.cluster.wait.aligned;" ::: "memory"); \
} while (0)

// grid = 128 CTAs: dir(2) x bslice(8) x hslice(8: cluster rank), 256 thr.
// blockIdx.x = ((dir*8 + bs) * 8) + hs ; cluster = the 8 hs CTAs of one (dir,bs).
// whh slice in registers; h_{t} exchanged via st.shared::cluster into peers' hbuf.
__global__ __launch_bounds__(256, 1) __cluster_dims__(8, 1, 1)
void lstm_layer(const float* __restrict__ gates,    // [2][S][B][1024] = Wx+b
                const float* __restrict__ whhF,     // [1024][256]
                const float* __restrict__ whhB,
                float* __restrict__ hout) {         // [S][B][512]
    __shared__ __align__(16) float hbuf[2][1024];   // [buf][4 batches][256]
    __shared__ __align__(16) float psum[1024];

    const int tid = threadIdx.x;
    const int bx = blockIdx.x;
    const int dir = bx >> 6;
    const int bs = (bx >> 3) & 7;
    const int hs = bx & 7;                      // == cluster rank
    const float* whh = dir ? whhB : whhF;

    const int jj = tid & 31;
    const int gg = (tid >> 5) & 3;
    const int q = tid >> 7;

    // whh slice into registers: gate-row = gg*256 + hs*32 + jj, K-half q
    unsigned long long w2[64];
    {
        const float* wptr = whh + ((size_t)(gg << 8) + (hs << 5) + jj) * 256 + (q << 7);
#pragma unroll
        for (int i = 0; i < 32; ++i) {
            ulonglong2 v = *(const ulonglong2*)(wptr + (i << 2));
            w2[2 * i] = v.x; w2[2 * i + 1] = v.y;
        }
    }

    // zero hbuf[0]
    *(float4*)&hbuf[0][tid << 2] = make_float4(0.f, 0.f, 0.f, 0.f);

    const int ob = (tid >> 5) & 3;              // tid<128: owned batch-in-slice
    const int obg = (bs << 2) + ob;             // global batch

    // peer smem addresses for this thread's h slot (buf 0 base)
    uint32_t rem[8];
    {
        uint32_t hb0 = (uint32_t)__cvta_generic_to_shared(&hbuf[0][0]);
        uint32_t slot = hb0 + (((ob << 8) + (hs << 5) + jj) << 2);
#pragma unroll
        for (int p = 0; p < 8; ++p)
            asm("mapa.shared::cluster.u32 %0, %1, %2;" : "=r"(rem[p]) : "r"(slot), "r"(p));
    }

    float c = 0.f;
    CLUSTER_SYNC_();

    for (int t = 0; t < S_LEN; ++t) {
        const int s = dir ? (S_LEN - 1 - t) : t;
        const int buf = t & 1, nxt = buf ^ 1;

        // gate prefetch (independent of hbuf)
        float gxi = 0.f, gxf = 0.f, gxg = 0.f, gxo = 0.f;
        if (tid < 128) {
            const float* gp = &gates[(size_t)(((dir * S_LEN + s) << 5) + obg) * 1024 + (hs << 5) + jj];
            gxi = gp[0]; gxf = gp[256]; gxg = gp[512]; gxo = gp[768];
        }

        unsigned long long a0 = 0ull, a1 = 0ull, a2 = 0ull, a3 = 0ull;
        const float* hb = &hbuf[buf][q << 7];
#pragma unroll
        for (int i = 0; i < 32; ++i) {
            ulonglong2 x0 = *(const ulonglong2*)(hb + (i << 2));
            ulonglong2 x1 = *(const ulonglong2*)(hb + 256 + (i << 2));
            ulonglong2 x2 = *(const ulonglong2*)(hb + 512 + (i << 2));
            ulonglong2 x3 = *(const ulonglong2*)(hb + 768 + (i << 2));
            vfma(a0, w2[2 * i], x0.x); vfma(a0, w2[2 * i + 1], x0.y);
            vfma(a1, w2[2 * i], x1.x); vfma(a1, w2[2 * i + 1], x1.y);
            vfma(a2, w2[2 * i], x2.x); vfma(a2, w2[2 * i + 1], x2.y);
            vfma(a3, w2[2 * i], x3.x); vfma(a3, w2[2 * i + 1], x3.y);
        }
        int pb = (gg << 5) + jj;
        psum[((q << 2) + 0) * 128 + pb] = red2(a0);
        psum[((q << 2) + 1) * 128 + pb] = red2(a1);
        psum[((q << 2) + 2) * 128 + pb] = red2(a2);
        psum[((q << 2) + 3) * 128 + pb] = red2(a3);
        __syncthreads();

        if (tid < 128) {
            float ri = psum[ob * 128 + jj]      + psum[(4 + ob) * 128 + jj];
            float rf = psum[ob * 128 + 32 + jj] + psum[(4 + ob) * 128 + 32 + jj];
            float rg = psum[ob * 128 + 64 + jj] + psum[(4 + ob) * 128 + 64 + jj];
            float ro = psum[ob * 128 + 96 + jj] + psum[(4 + ob) * 128 + 96 + jj];
            float iv = sigm(gxi + ri);
            float fv = sigm(gxf + rf);
            float gv = tanhf(gxg + rg);
            float ov = sigm(gxo + ro);
            c = fv * c + iv * gv;
            float h = ov * tanhf(c);
            // broadcast h into all 8 cluster CTAs' hbuf[nxt]
            uint32_t boff = (uint32_t)nxt << 12;
#pragma unroll
            for (int p = 0; p < 8; ++p)
                asm volatile("st.shared::cluster.f32 [%0], %1;"
                             :: "r"(rem[p] + boff), "f"(h) : "memory");
            hout[(size_t)((s << 5) + obg) * 512 + (dir << 8) + (hs << 5) + jj] = h;
        }
        CLUSTER_SYNC_();
    }
}

// ---------------- feats = h1 @ w_out^T + b_out ----------------
__global__ __launch_bounds__(256)
void feats_kernel(const float* __restrict__ h,
                  const float* __restrict__ w_out,
                  const float* __restrict__ b_out,
                  float* __restrict__ feats) {
    __shared__ float ws[NTAG * 512];
    int tid = threadIdx.x;
    for (int i = tid; i < NTAG * 512; i += 256) ws[i] = w_out[i];
    __syncthreads();
    int warp = tid >> 5, lane = tid & 31;
    int m = blockIdx.x * 8 + warp;          // 0..16383
    float hreg[16];
#pragma unroll
    for (int i = 0; i < 16; ++i) hreg[i] = h[(size_t)m * 512 + i * 32 + lane];
#pragma unroll
    for (int tg = 0; tg < NTAG; ++tg) {
        float acc = 0.f;
#pragma unroll
        for (int i = 0; i < 16; ++i) acc += hreg[i] * ws[tg * 512 + i * 32 + lane];
#pragma unroll
        for (int off = 16; off; off >>= 1) acc += __shfl_down_sync(0xffffffffu, acc, off);
        if (lane == 0) feats[(size_t)m * NTAG + tg] = acc + b_out[tg];
    }
}

// ---------------- Viterbi (1 warp per batch) ----------------
__global__ __launch_bounds__(32)
void viterbi_kernel(const float* __restrict__ feats,
                    const float* __restrict__ trans,
                    float* __restrict__ out) {
    __shared__ unsigned char bps[S_LEN][16];
    int b = blockIdx.x, t = threadIdx.x;
    int tc = (t < NTAG) ? t : NTAG - 1;
    float tr[NTAG];
#pragma unroll
    for (int p = 0; p < NTAG; ++p) tr[p] = trans[tc * NTAG + p];
    float fv = (t == START_TAG) ? 0.f : NEGV;

    for (int s = 0; s < S_LEN; ++s) {
        float best = -3.4e38f; int bp = 0;
#pragma unroll
        for (int p = 0; p < NTAG; ++p) {
            float fp = __shfl_sync(0xffffffffu, fv, p);
            float v = fp + tr[p];
            if (v > best) { best = v; bp = p; }
        }
        float feat = (t < NTAG) ? feats[(size_t)((s << 5) + b) * NTAG + t] : 0.f;
        fv = best + feat;
        if (t < NTAG) bps[s][t] = (unsigned char)bp;
    }

    float term = (t < NTAG) ? fv + trans[STOP_TAG * NTAG + t] : -3.4e38f;
    int idx = t;
#pragma unroll
    for (int off = 16; off; off >>= 1) {
        float ov = __shfl_down_sync(0xffffffffu, term, off);
        int oi = __shfl_down_sync(0xffffffffu, idx, off);
        if (ov > term || (ov == term && oi < idx)) { term = ov; idx = oi; }
    }
    if (t == 0) {
        out[b] = term;
        int tag = idx;
        for (int s = S_LEN - 1; s >= 0; --s) {
            out[32 + b * S_LEN + s] = (float)tag;
            tag = bps[s][tag];
        }
    }
}

// ---------------- launcher ----------------
extern "C" void kernel_launch(void* const* d_in, const int* in_sizes, int n_in,
                              void* d_out, int out_size) {
    const int*   x      = (const int*)d_in[0];
    const float* emb    = (const float*)d_in[2];
    const float* wih0f  = (const float*)d_in[3];
    const float* whh0f  = (const float*)d_in[4];
    const float* b0f    = (const float*)d_in[5];
    const float* wih0b  = (const float*)d_in[6];
    const float* whh0b  = (const float*)d_in[7];
    const float* b0b    = (const float*)d_in[8];
    const float* wih1f  = (const float*)d_in[9];
    const float* whh1f  = (const float*)d_in[10];
    const float* b1f    = (const float*)d_in[11];
    const float* wih1b  = (const float*)d_in[12];
    const float* whh1b  = (const float*)d_in[13];
    const float* b1b    = (const float*)d_in[14];
    const float* w_out  = (const float*)d_in[15];
    const float* b_out  = (const float*)d_in[16];
    const float* trans  = (const float*)d_in[17];
    float* out = (float*)d_out;

    float* xe = nullptr; float* gates = nullptr; float* h0 = nullptr;
    float* h1 = nullptr; float* feats = nullptr;
    cudaGetSymbolAddress((void**)&xe, g_xe);
    cudaGetSymbolAddress((void**)&gates, g_gates);
    cudaGetSymbolAddress((void**)&h0, g_h0);
    cudaGetSymbolAddress((void**)&h1, g_h1);
    cudaGetSymbolAddress((void**)&feats, g_feats);

    const size_t dirStride = (size_t)S_LEN * BATCH * 1024;

    embed_kernel<<<4096, 256>>>(x, emb, xe);

    sgemm_bias<<<dim3(8, 128), 256>>>(xe, wih0f, b0f, gates, HID);
    sgemm_bias<<<dim3(8, 128), 256>>>(xe, wih0b, b0b, gates + dirStride, HID);
    lstm_layer<<<NCTA_LSTM, 256>>>(gates, whh0f, whh0b, h0);

    sgemm_bias<<<dim3(8, 128), 256>>>(h0, wih1f, b1f, gates, 2 * HID);
    sgemm_bias<<<dim3(8, 128), 256>>>(h0, wih1b, b1b, gates + dirStride, 2 * HID);
    lstm_layer<<<NCTA_LSTM, 256>>>(gates, whh1f, whh1b, h1);

    feats_kernel<<<2048, 256>>>(h1, w_out, b_out, feats);
    viterbi_kernel<<<BATCH, 32>>>(feats, trans, out);
}